// round 7
// baseline (speedup 1.0000x reference)
#include <cuda_runtime.h>

#define S_TOK     2304
#define D_MODEL   3072
#define NHEAD     24
#define HDIM      128
#define BLOCK_TOK 2048
#define CONDN     256
#define RANKN     128
#define T_IPN     128
#define D_IPN     4096
#define EPSV      1e-5f
// (1/sqrt(128)) * log2(e): softmax computed in exp2 domain
#define QSCALE    0.1275173e+0f

// ---------------- device scratch ----------------
__device__ float g_q[S_TOK * D_MODEL];
__device__ float g_k[S_TOK * D_MODEL];
__device__ float g_v[S_TOK * D_MODEL];
__device__ float g_kip[T_IPN * D_MODEL];
__device__ float g_vip[T_IPN * D_MODEL];
__device__ float g_lt[3 * CONDN * RANKN];
// RNA-tf32-rounded operand copies (GEMM loops run cvt-free)
__device__ float g_xr[S_TOK * D_MODEL];
__device__ float g_wqr[D_MODEL * D_MODEL];
__device__ float g_wkr[D_MODEL * D_MODEL];
__device__ float g_wvr[D_MODEL * D_MODEL];
__device__ float g_imgr[T_IPN * D_IPN];
__device__ float g_wkipr[D_MODEL * D_IPN];
__device__ float g_wvipr[D_MODEL * D_IPN];
__device__ float g_ldr[6 * RANKN * D_MODEL];   // qd,kd,vd,qu,ku,vu rounded

// ---------------- helpers ----------------
__device__ __forceinline__ unsigned f2tf(float f) {
    unsigned u;
    asm("cvt.rna.tf32.f32 %0, %1;" : "=r"(u) : "f"(f));
    return u;
}
__device__ __forceinline__ void mma8(float* c, const unsigned* a, unsigned b0, unsigned b1) {
    asm volatile(
        "mma.sync.aligned.m16n8k8.row.col.f32.tf32.tf32.f32 "
        "{%0,%1,%2,%3}, {%4,%5,%6,%7}, {%8,%9}, {%0,%1,%2,%3};"
        : "+f"(c[0]), "+f"(c[1]), "+f"(c[2]), "+f"(c[3])
        : "r"(a[0]), "r"(a[1]), "r"(a[2]), "r"(a[3]), "r"(b0), "r"(b1));
}
__device__ __forceinline__ void cpa16(unsigned dst, const void* src) {
    asm volatile("cp.async.cg.shared.global [%0], [%1], 16;" :: "r"(dst), "l"(src));
}
__device__ __forceinline__ void cp_commit() { asm volatile("cp.async.commit_group;"); }
__device__ __forceinline__ void cp_wait0() { asm volatile("cp.async.wait_group 0;"); }

// ---------------- RNA tf32 rounding pre-pass (13 buffers) ----------------
struct R16 { const float* s[13]; float* d[13]; int n[13]; };
__global__ void round_tf32_kernel(R16 P) {
    const int y = blockIdx.y;
    const float4* src = (const float4*)P.s[y];
    float4* dst = (float4*)P.d[y];
    const int n4 = P.n[y] >> 2;
    for (int i = blockIdx.x * blockDim.x + threadIdx.x; i < n4; i += gridDim.x * blockDim.x) {
        float4 v = src[i];
        v.x = __uint_as_float(f2tf(v.x));
        v.y = __uint_as_float(f2tf(v.y));
        v.z = __uint_as_float(f2tf(v.z));
        v.w = __uint_as_float(f2tf(v.w));
        dst[i] = v;
    }
}

// ============ batched GEMM (cvt-free): C[M,N] (+)= A[M,K] @ B[N,K]^T + bias ============
// Inputs MUST be pre-rounded tf32 bit patterns. 128x128 tile, BK=16, 256 thr,
// warp tile 64x32, cp.async double buffer, smem [mn][k] stride 20 (conflict-free).
// rnd[z]: round output to tf32 at store (for LoRA-down -> LoRA-up chain).
struct GemmB {
    const float* A[8]; const float* Bm[8]; const float* bias[8]; float* C[8];
    int M[8], N[8], K[8], rnd[8];
};

template <bool ACC>
__global__ __launch_bounds__(256, 2) void gemm_tc(GemmB P)
{
    __shared__ unsigned As[2][2560];
    __shared__ unsigned Bs[2][2560];
    const int z = blockIdx.z;
    const int M = P.M[z], N = P.N[z], K = P.K[z];
    const int bm = blockIdx.y << 7, bn = blockIdx.x << 7;
    if (bm >= M || bn >= N) return;
    const float* A = P.A[z];
    const float* Bw = P.Bm[z];
    const float* bias = P.bias[z];
    float* C = P.C[z];
    const int rndC = P.rnd[z];

    const int tid = threadIdx.x;
    const int lw = tid & 31, w = tid >> 5, g = lw >> 2, t = lw & 3;
    const int wm = w & 1, wn = w >> 1;   // 2 x 4 warp grid, warp tile 64x32

    const int lrow = tid >> 1, lseg = (tid & 1) * 8;
    const float* Arow = A + (size_t)(bm + lrow) * K + lseg;
    const float* Brow = Bw + (size_t)(bn + lrow) * K + lseg;
    const unsigned as_u = (unsigned)__cvta_generic_to_shared(As) + (lrow * 20 + lseg) * 4;
    const unsigned bs_u = (unsigned)__cvta_generic_to_shared(Bs) + (lrow * 20 + lseg) * 4;

    float acc[4][4][4];
#pragma unroll
    for (int mt = 0; mt < 4; mt++)
#pragma unroll
        for (int nt = 0; nt < 4; nt++)
#pragma unroll
            for (int i = 0; i < 4; i++) acc[mt][nt][i] = 0.f;

    cpa16(as_u, Arow);        cpa16(as_u + 16, Arow + 4);
    cpa16(bs_u, Brow);        cpa16(bs_u + 16, Brow + 4);
    cp_commit();

    const int niter = K >> 4;
    for (int it = 0; it < niter; it++) {
        const int cur = it & 1;
        cp_wait0();
        __syncthreads();
        if (it + 1 < niter) {
            const int k0 = (it + 1) << 4;
            const unsigned off = (unsigned)((cur ^ 1) * 2560 * 4);
            cpa16(as_u + off, Arow + k0);      cpa16(as_u + off + 16, Arow + k0 + 4);
            cpa16(bs_u + off, Brow + k0);      cpa16(bs_u + off + 16, Brow + k0 + 4);
            cp_commit();
        }
#pragma unroll
        for (int ks = 0; ks < 2; ks++) {
            const int kr = ks * 8 + t;
            unsigned af[4][4], bf[4][2];
#pragma unroll
            for (int mt = 0; mt < 4; mt++) {
                const unsigned* ap = &As[cur][(wm * 64 + mt * 16 + g) * 20 + kr];
                af[mt][0] = ap[0];
                af[mt][1] = ap[160];
                af[mt][2] = ap[4];
                af[mt][3] = ap[164];
            }
#pragma unroll
            for (int nt = 0; nt < 4; nt++) {
                const unsigned* bp = &Bs[cur][(wn * 32 + nt * 8 + g) * 20 + kr];
                bf[nt][0] = bp[0];
                bf[nt][1] = bp[4];
            }
#pragma unroll
            for (int mt = 0; mt < 4; mt++)
#pragma unroll
                for (int nt = 0; nt < 4; nt++)
                    mma8(acc[mt][nt], af[mt], bf[nt][0], bf[nt][1]);
        }
        __syncthreads();
    }

#pragma unroll
    for (int mt = 0; mt < 4; mt++) {
        const int r0 = bm + wm * 64 + mt * 16 + g;
        const int r1 = r0 + 8;
#pragma unroll
        for (int nt = 0; nt < 4; nt++) {
            const int cc = bn + wn * 32 + nt * 8 + 2 * t;
            float2 v0 = make_float2(acc[mt][nt][0], acc[mt][nt][1]);
            float2 v1 = make_float2(acc[mt][nt][2], acc[mt][nt][3]);
            if (bias) {
                float bx = bias[cc], by = bias[cc + 1];
                v0.x += bx; v0.y += by; v1.x += bx; v1.y += by;
            }
            float* p0 = C + (size_t)r0 * N + cc;
            float* p1 = C + (size_t)r1 * N + cc;
            if (ACC) {
                float2 e0 = *(const float2*)p0, e1 = *(const float2*)p1;
                v0.x += e0.x; v0.y += e0.y; v1.x += e1.x; v1.y += e1.y;
            }
            if (rndC) {
                v0.x = __uint_as_float(f2tf(v0.x));
                v0.y = __uint_as_float(f2tf(v0.y));
                v1.x = __uint_as_float(f2tf(v1.x));
                v1.y = __uint_as_float(f2tf(v1.y));
            }
            *(float2*)p0 = v0;
            *(float2*)p1 = v1;
        }
    }
}

// ------- fused norm/round: y=0 q(norm+rope+w,*QSCALE) 1=k 2=kip(norm) 3=v 4=vip -------
__global__ void norm_all_kernel(float* q, float* k, float* kip, float* v, float* vip,
                                const float* wq, const float* wk,
                                const float* cs, const float* sn)
{
    const int y = blockIdx.y;
    float* tp; const float* wp = nullptr;
    int rows = S_TOK, mode = 2;
    float sc = 1.f;
    if (y == 0)      { tp = q;   wp = wq; mode = 0; sc = QSCALE; }
    else if (y == 1) { tp = k;   wp = wk; mode = 0; }
    else if (y == 2) { tp = kip; rows = T_IPN; mode = 1; }
    else if (y == 3) { tp = v; }
    else             { tp = vip; rows = T_IPN; }

    int gwarp = (blockIdx.x * blockDim.x + threadIdx.x) >> 5;
    int lane = threadIdx.x & 31;
    if (gwarp >= rows * NHEAD) return;
    int s = gwarp / NHEAD, h = gwarp % NHEAD;
    float* p = tp + (size_t)s * D_MODEL + h * HDIM + lane * 4;
    float4 x = *(const float4*)p;
    if (mode <= 1) {
        float ss = x.x * x.x + x.y * x.y + x.z * x.z + x.w * x.w;
#pragma unroll
        for (int off = 16; off >= 1; off >>= 1) ss += __shfl_xor_sync(0xffffffffu, ss, off);
        float inv = rsqrtf(ss * (1.0f / HDIM) + EPSV);
        x.x *= inv; x.y *= inv; x.z *= inv; x.w *= inv;
        if (wp) {
            float4 wv = *(const float4*)(wp + lane * 4);
            x.x *= wv.x; x.y *= wv.y; x.z *= wv.z; x.w *= wv.w;
        }
        if (mode == 0) {
            float4 c = *(const float4*)(cs + (size_t)s * HDIM + lane * 4);
            float4 v2 = *(const float4*)(sn + (size_t)s * HDIM + lane * 4);
            float o0 = x.x * c.x - x.y * v2.x;
            float o1 = x.y * c.y + x.x * v2.y;
            float o2 = x.z * c.z - x.w * v2.z;
            float o3 = x.w * c.w + x.z * v2.w;
            x.x = o0; x.y = o1; x.z = o2; x.w = o3;
        }
    }
    x.x = __uint_as_float(f2tf(x.x * sc));
    x.y = __uint_as_float(f2tf(x.y * sc));
    x.z = __uint_as_float(f2tf(x.z * sc));
    x.w = __uint_as_float(f2tf(x.w * sc));
    *(float4*)p = x;
}

// ============ fused flash attention (tf32, pre-rounded operands) ============
// Bq=128 (8 warps x 16 q), Bk=64, HD=128. Phase 0: main (block-masked) writes Out;
// Phase 1: IP (kv=128) RMW-adds into Out. Q fragments live across both phases.
__global__ __launch_bounds__(256, 1) void attn_tc(
    const unsigned* __restrict__ Q, const unsigned* __restrict__ Km,
    const unsigned* __restrict__ Vm, const unsigned* __restrict__ Ki,
    const unsigned* __restrict__ Vi, float* __restrict__ Out)
{
    extern __shared__ unsigned smu[];
    unsigned* Ks = smu;
    unsigned* Vs = smu + 2 * 8448;
    unsigned* Ps = Vs + 2 * 8704;

    const int tid = threadIdx.x;
    const int l = tid & 31, w = tid >> 5;
    const int g = l >> 2, t = l & 3;
    const int h = blockIdx.y;
    const int q0 = blockIdx.x << 7;
    const int qr = q0 + w * 16 + g;

    unsigned qf[16][4];
    {
        const unsigned* qp = Q + (size_t)qr * D_MODEL + h * HDIM;
        const unsigned* qp8 = qp + (size_t)8 * D_MODEL;
#pragma unroll
        for (int ks = 0; ks < 16; ks++) {
            const int cb = ks * 8 + t;
            qf[ks][0] = qp[cb];
            qf[ks][1] = qp8[cb];
            qf[ks][2] = qp[cb + 4];
            qf[ks][3] = qp8[cb + 4];
        }
    }

    const int row = tid >> 2, seg = (tid & 3) * 32;
    const unsigned ks_u = (unsigned)__cvta_generic_to_shared(Ks) + (row * 132 + seg) * 4;
    const unsigned vs_u = (unsigned)__cvta_generic_to_shared(Vs) + (row * 136 + seg) * 4;
    float* op0 = Out + (size_t)qr * D_MODEL + h * HDIM;
    float* op1 = op0 + (size_t)8 * D_MODEL;

#pragma unroll 1
    for (int ph = 0; ph < 2; ph++) {
        const unsigned* Kb = ph ? Ki : Km;
        const unsigned* Vb = ph ? Vi : Vm;
        const int kt0 = (ph == 0 && q0 >= BLOCK_TOK) ? BLOCK_TOK : 0;
        const int ntiles = ((ph ? T_IPN : S_TOK) - kt0) >> 6;

        float o[16][4];
#pragma unroll
        for (int nt = 0; nt < 16; nt++)
#pragma unroll
            for (int i = 0; i < 4; i++) o[nt][i] = 0.f;
        float mrow0 = -1e30f, mrow1 = -1e30f, lrow0 = 0.f, lrow1 = 0.f;

        __syncthreads();
        {
            const unsigned* kg = Kb + (size_t)(kt0 + row) * D_MODEL + h * HDIM + seg;
            const unsigned* vg = Vb + (size_t)(kt0 + row) * D_MODEL + h * HDIM + seg;
#pragma unroll
            for (int c = 0; c < 8; c++) {
                cpa16(ks_u + c * 16, kg + c * 4);
                cpa16(vs_u + c * 16, vg + c * 4);
            }
            cp_commit();
        }

        for (int it = 0; it < ntiles; it++) {
            const int cur = it & 1;
            cp_wait0();
            __syncthreads();
            if (it + 1 < ntiles) {
                const int kt = kt0 + (it + 1) * 64;
                const unsigned* kg = Kb + (size_t)(kt + row) * D_MODEL + h * HDIM + seg;
                const unsigned* vg = Vb + (size_t)(kt + row) * D_MODEL + h * HDIM + seg;
                const unsigned ko = ks_u + (cur ^ 1) * 8448 * 4;
                const unsigned vo = vs_u + (cur ^ 1) * 8704 * 4;
#pragma unroll
                for (int c = 0; c < 8; c++) {
                    cpa16(ko + c * 16, kg + c * 4);
                    cpa16(vo + c * 16, vg + c * 4);
                }
                cp_commit();
            }
            const unsigned* Kc = Ks + cur * 8448;
            const unsigned* Vc = Vs + cur * 8704;

            float s[8][4];
#pragma unroll
            for (int nt = 0; nt < 8; nt++)
#pragma unroll
                for (int i = 0; i < 4; i++) s[nt][i] = 0.f;
#pragma unroll
            for (int ks = 0; ks < 16; ks++) {
                const int kr = ks * 8 + t;
#pragma unroll
                for (int nt = 0; nt < 8; nt++) {
                    const unsigned* kp2 = Kc + (nt * 8 + g) * 132 + kr;
                    mma8(s[nt], qf[ks], kp2[0], kp2[4]);
                }
            }

            float mx0 = -1e30f, mx1 = -1e30f;
#pragma unroll
            for (int nt = 0; nt < 8; nt++) {
                mx0 = fmaxf(mx0, fmaxf(s[nt][0], s[nt][1]));
                mx1 = fmaxf(mx1, fmaxf(s[nt][2], s[nt][3]));
            }
            mx0 = fmaxf(mx0, __shfl_xor_sync(0xffffffffu, mx0, 1));
            mx0 = fmaxf(mx0, __shfl_xor_sync(0xffffffffu, mx0, 2));
            mx1 = fmaxf(mx1, __shfl_xor_sync(0xffffffffu, mx1, 1));
            mx1 = fmaxf(mx1, __shfl_xor_sync(0xffffffffu, mx1, 2));
            const float mn0 = fmaxf(mrow0, mx0), mn1 = fmaxf(mrow1, mx1);
            const float al0 = exp2f(mrow0 - mn0), al1 = exp2f(mrow1 - mn1);
            mrow0 = mn0; mrow1 = mn1;

            float sum0 = 0.f, sum1 = 0.f;
#pragma unroll
            for (int nt = 0; nt < 8; nt++) {
                float p0 = exp2f(s[nt][0] - mn0);
                float p1 = exp2f(s[nt][1] - mn0);
                float p2 = exp2f(s[nt][2] - mn1);
                float p3 = exp2f(s[nt][3] - mn1);
                sum0 += p0 + p1;
                sum1 += p2 + p3;
                const int nb = nt * 8 + 2 * t;
                Ps[(nb + 0) * 136 + w * 16 + g]     = f2tf(p0);
                Ps[(nb + 1) * 136 + w * 16 + g]     = f2tf(p1);
                Ps[(nb + 0) * 136 + w * 16 + g + 8] = f2tf(p2);
                Ps[(nb + 1) * 136 + w * 16 + g + 8] = f2tf(p3);
            }
            sum0 += __shfl_xor_sync(0xffffffffu, sum0, 1);
            sum0 += __shfl_xor_sync(0xffffffffu, sum0, 2);
            sum1 += __shfl_xor_sync(0xffffffffu, sum1, 1);
            sum1 += __shfl_xor_sync(0xffffffffu, sum1, 2);
            lrow0 = lrow0 * al0 + sum0;
            lrow1 = lrow1 * al1 + sum1;
#pragma unroll
            for (int nt = 0; nt < 16; nt++) {
                o[nt][0] *= al0; o[nt][1] *= al0;
                o[nt][2] *= al1; o[nt][3] *= al1;
            }
            __syncwarp();

#pragma unroll
            for (int ks = 0; ks < 8; ks++) {
                const int kr = ks * 8 + t;
                unsigned pa[4];
                pa[0] = Ps[kr * 136 + w * 16 + g];
                pa[1] = Ps[kr * 136 + w * 16 + g + 8];
                pa[2] = Ps[(kr + 4) * 136 + w * 16 + g];
                pa[3] = Ps[(kr + 4) * 136 + w * 16 + g + 8];
#pragma unroll
                for (int nt = 0; nt < 16; nt++) {
                    const unsigned* vp2 = Vc + kr * 136 + nt * 8 + g;
                    mma8(o[nt], pa, vp2[0], vp2[4 * 136]);
                }
            }
        }

        const float inv0 = 1.f / lrow0, inv1 = 1.f / lrow1;
#pragma unroll
        for (int nt = 0; nt < 16; nt++) {
            const int cc = nt * 8 + 2 * t;
            float2 v0 = make_float2(o[nt][0] * inv0, o[nt][1] * inv0);
            float2 v1 = make_float2(o[nt][2] * inv1, o[nt][3] * inv1);
            if (ph == 1) {
                float2 e0 = *(const float2*)(op0 + cc);
                float2 e1 = *(const float2*)(op1 + cc);
                v0.x += e0.x; v0.y += e0.y; v1.x += e1.x; v1.y += e1.y;
            }
            *(float2*)(op0 + cc) = v0;
            *(float2*)(op1 + cc) = v1;
        }
    }
}

// ---------------- host launcher ----------------
extern "C" void kernel_launch(void* const* d_in, const int* in_sizes, int n_in,
                              void* d_out, int out_size)
{
    (void)in_sizes; (void)n_in; (void)out_size;
    const float* x    = (const float*)d_in[0];
    const float* img  = (const float*)d_in[1];
    const float* cosr = (const float*)d_in[2];
    const float* sinr = (const float*)d_in[3];
    const float* Wq   = (const float*)d_in[4];
    const float* bq   = (const float*)d_in[5];
    const float* Wk   = (const float*)d_in[6];
    const float* bk   = (const float*)d_in[7];
    const float* Wv   = (const float*)d_in[8];
    const float* bv   = (const float*)d_in[9];
    const float* qd   = (const float*)d_in[10];
    const float* qu   = (const float*)d_in[11];
    const float* kd   = (const float*)d_in[12];
    const float* ku   = (const float*)d_in[13];
    const float* vd   = (const float*)d_in[14];
    const float* vu   = (const float*)d_in[15];
    const float* nqw  = (const float*)d_in[16];
    const float* nkw  = (const float*)d_in[17];
    const float* Wkip = (const float*)d_in[18];
    const float* Wvip = (const float*)d_in[19];
    float* out = (float*)d_out;

    float *q, *k, *v, *kip, *vip, *lt;
    float *xr, *wqr, *wkr, *wvr, *imgr, *wkipr, *wvipr, *ldr;
    cudaGetSymbolAddress((void**)&q,     g_q);
    cudaGetSymbolAddress((void**)&k,     g_k);
    cudaGetSymbolAddress((void**)&v,     g_v);
    cudaGetSymbolAddress((void**)&kip,   g_kip);
    cudaGetSymbolAddress((void**)&vip,   g_vip);
    cudaGetSymbolAddress((void**)&lt,    g_lt);
    cudaGetSymbolAddress((void**)&xr,    g_xr);
    cudaGetSymbolAddress((void**)&wqr,   g_wqr);
    cudaGetSymbolAddress((void**)&wkr,   g_wkr);
    cudaGetSymbolAddress((void**)&wvr,   g_wvr);
    cudaGetSymbolAddress((void**)&imgr,  g_imgr);
    cudaGetSymbolAddress((void**)&wkipr, g_wkipr);
    cudaGetSymbolAddress((void**)&wvipr, g_wvipr);
    cudaGetSymbolAddress((void**)&ldr,   g_ldr);

    const int LW = RANKN * D_MODEL;
    float* qdr = ldr;            float* kdr = ldr + LW;     float* vdr = ldr + 2 * LW;
    float* qur = ldr + 3 * LW;   float* kur = ldr + 4 * LW; float* vur = ldr + 5 * LW;

    // 1) RNA tf32 rounding pre-pass (13 buffers)
    {
        R16 R;
        R.s[0]  = x;    R.d[0]  = xr;    R.n[0]  = S_TOK * D_MODEL;
        R.s[1]  = Wq;   R.d[1]  = wqr;   R.n[1]  = D_MODEL * D_MODEL;
        R.s[2]  = Wk;   R.d[2]  = wkr;   R.n[2]  = D_MODEL * D_MODEL;
        R.s[3]  = Wv;   R.d[3]  = wvr;   R.n[3]  = D_MODEL * D_MODEL;
        R.s[4]  = img;  R.d[4]  = imgr;  R.n[4]  = T_IPN * D_IPN;
        R.s[5]  = Wkip; R.d[5]  = wkipr; R.n[5]  = D_MODEL * D_IPN;
        R.s[6]  = Wvip; R.d[6]  = wvipr; R.n[6]  = D_MODEL * D_IPN;
        R.s[7]  = qd;   R.d[7]  = qdr;   R.n[7]  = LW;
        R.s[8]  = kd;   R.d[8]  = kdr;   R.n[8]  = LW;
        R.s[9]  = vd;   R.d[9]  = vdr;   R.n[9]  = LW;
        R.s[10] = qu;   R.d[10] = qur;   R.n[10] = LW;
        R.s[11] = ku;   R.d[11] = kur;   R.n[11] = LW;
        R.s[12] = vu;   R.d[12] = vur;   R.n[12] = LW;
        round_tf32_kernel<<<dim3(512, 13), 256>>>(R);
    }
    const float* xcr = xr + (size_t)BLOCK_TOK * D_MODEL;

    // 2) mega GEMM: z 0-2 QKV, z 3-5 LoRA-down (rounded out), z 6-7 IP projections
    {
        GemmB P;
        P.A[0] = xr; P.A[1] = xr; P.A[2] = xr;
        P.Bm[0] = wqr; P.Bm[1] = wkr; P.Bm[2] = wvr;
        P.bias[0] = bq; P.bias[1] = bk; P.bias[2] = bv;
        P.C[0] = q;  P.C[1] = k;  P.C[2] = v;
        P.M[0] = P.M[1] = P.M[2] = S_TOK;
        P.N[0] = P.N[1] = P.N[2] = D_MODEL;
        P.K[0] = P.K[1] = P.K[2] = D_MODEL;
        P.rnd[0] = P.rnd[1] = P.rnd[2] = 0;
        P.A[3] = xcr; P.A[4] = xcr; P.A[5] = xcr;
        P.Bm[3] = qdr; P.Bm[4] = kdr; P.Bm[5] = vdr;
        P.bias[3] = P.bias[4] = P.bias[5] = nullptr;
        P.C[3] = lt; P.C[4] = lt + CONDN * RANKN; P.C[5] = lt + 2 * CONDN * RANKN;
        P.M[3] = P.M[4] = P.M[5] = CONDN;
        P.N[3] = P.N[4] = P.N[5] = RANKN;
        P.K[3] = P.K[4] = P.K[5] = D_MODEL;
        P.rnd[3] = P.rnd[4] = P.rnd[5] = 1;
        P.A[6] = imgr; P.A[7] = imgr;
        P.Bm[6] = wkipr; P.Bm[7] = wvipr;
        P.bias[6] = P.bias[7] = nullptr;
        P.C[6] = kip; P.C[7] = vip;
        P.M[6] = P.M[7] = T_IPN;
        P.N[6] = P.N[7] = D_MODEL;
        P.K[6] = P.K[7] = D_IPN;
        P.rnd[6] = P.rnd[7] = 0;
        gemm_tc<false><<<dim3(D_MODEL / 128, S_TOK / 128, 8), 256>>>(P);
    }
    // 3) LoRA up: accumulate into q/k/v cond rows (alpha/rank * lora_w = 1)
    {
        GemmB P;
        P.A[0] = lt; P.A[1] = lt + CONDN * RANKN; P.A[2] = lt + 2 * CONDN * RANKN;
        P.Bm[0] = qur; P.Bm[1] = kur; P.Bm[2] = vur;
        P.bias[0] = P.bias[1] = P.bias[2] = nullptr;
        P.C[0] = q + (size_t)BLOCK_TOK * D_MODEL;
        P.C[1] = k + (size_t)BLOCK_TOK * D_MODEL;
        P.C[2] = v + (size_t)BLOCK_TOK * D_MODEL;
        for (int i = 0; i < 3; i++) { P.M[i] = CONDN; P.N[i] = D_MODEL; P.K[i] = RANKN; P.rnd[i] = 0; }
        for (int i = 3; i < 8; i++) { P.A[i] = nullptr; P.Bm[i] = nullptr; P.bias[i] = nullptr; P.C[i] = nullptr; P.M[i] = 0; P.N[i] = 0; P.K[i] = 16; P.rnd[i] = 0; }
        gemm_tc<true><<<dim3(D_MODEL / 128, CONDN / 128, 3), 256>>>(P);
    }
    // 4) fused norms + tf32 pre-rounding: q(+QSCALE), k, kip, v, vip
    norm_all_kernel<<<dim3((S_TOK * NHEAD * 32 + 255) / 256, 5), 256>>>(q, k, kip, v, vip, nqw, nkw, cosr, sinr);
    // 5) fused attention: main (masked) + IP phase
    {
        size_t smem = (size_t)(2 * 8448 + 2 * 8704 + 64 * 136) * 4;
        cudaFuncSetAttribute(attn_tc, cudaFuncAttributeMaxDynamicSharedMemorySize, (int)smem);
        attn_tc<<<dim3(S_TOK / 128, NHEAD), 256, smem>>>(
            (const unsigned*)q, (const unsigned*)k, (const unsigned*)v,
            (const unsigned*)kip, (const unsigned*)vip, out);
    }
}

// round 8
// speedup vs baseline: 1.0541x; 1.0541x over previous
#include <cuda_runtime.h>

#define S_TOK     2304
#define D_MODEL   3072
#define NHEAD     24
#define HDIM      128
#define BLOCK_TOK 2048
#define CONDN     256
#define RANKN     128
#define T_IPN     128
#define D_IPN     4096
#define EPSV      1e-5f
// (1/sqrt(128)) * log2(e): softmax computed in exp2 domain
#define QSCALE    0.1275173e+0f
#define BIGROW    0x7fffffff

// ---------------- device scratch ----------------
__device__ float g_q[S_TOK * D_MODEL];
__device__ float g_k[S_TOK * D_MODEL];
__device__ float g_v[S_TOK * D_MODEL];
__device__ float g_kip[T_IPN * D_MODEL];
__device__ float g_vip[T_IPN * D_MODEL];
__device__ float g_lt[3 * CONDN * RANKN];
// RNA-tf32-rounded operand copies (GEMM loops run cvt-free)
__device__ float g_xr[S_TOK * D_MODEL];
__device__ float g_wqr[D_MODEL * D_MODEL];
__device__ float g_wkr[D_MODEL * D_MODEL];
__device__ float g_wvr[D_MODEL * D_MODEL];
__device__ float g_imgr[T_IPN * D_IPN];
__device__ float g_wkipr[D_MODEL * D_IPN];
__device__ float g_wvipr[D_MODEL * D_IPN];
__device__ float g_ldr[6 * RANKN * D_MODEL];   // qd,kd,vd,qu,ku,vu rounded

// ---------------- helpers ----------------
__device__ __forceinline__ unsigned f2tf(float f) {
    unsigned u;
    asm("cvt.rna.tf32.f32 %0, %1;" : "=r"(u) : "f"(f));
    return u;
}
__device__ __forceinline__ void mma8(float* c, const unsigned* a, unsigned b0, unsigned b1) {
    asm volatile(
        "mma.sync.aligned.m16n8k8.row.col.f32.tf32.tf32.f32 "
        "{%0,%1,%2,%3}, {%4,%5,%6,%7}, {%8,%9}, {%0,%1,%2,%3};"
        : "+f"(c[0]), "+f"(c[1]), "+f"(c[2]), "+f"(c[3])
        : "r"(a[0]), "r"(a[1]), "r"(a[2]), "r"(a[3]), "r"(b0), "r"(b1));
}
__device__ __forceinline__ void cpa16(unsigned dst, const void* src) {
    asm volatile("cp.async.cg.shared.global [%0], [%1], 16;" :: "r"(dst), "l"(src));
}
__device__ __forceinline__ void cp_commit() { asm volatile("cp.async.commit_group;"); }
__device__ __forceinline__ void cp_wait0() { asm volatile("cp.async.wait_group 0;"); }
__device__ __forceinline__ void cp_wait1() { asm volatile("cp.async.wait_group 1;"); }

// ---------------- RNA tf32 rounding pre-pass (13 buffers) ----------------
struct R16 { const float* s[13]; float* d[13]; int n[13]; };
__global__ void round_tf32_kernel(R16 P) {
    const int y = blockIdx.y;
    const float4* src = (const float4*)P.s[y];
    float4* dst = (float4*)P.d[y];
    const int n4 = P.n[y] >> 2;
    for (int i = blockIdx.x * blockDim.x + threadIdx.x; i < n4; i += gridDim.x * blockDim.x) {
        float4 v = src[i];
        v.x = __uint_as_float(f2tf(v.x));
        v.y = __uint_as_float(f2tf(v.y));
        v.z = __uint_as_float(f2tf(v.z));
        v.w = __uint_as_float(f2tf(v.w));
        dst[i] = v;
    }
}

// ============ batched GEMM (cvt-free, 3-stage, fused norm epilogue) ============
// C[M,N] (+)= A[M,K] @ B[N,K]^T + bias. 128x128 tile, BK=16, 256 thr, warp tile
// 64x32, 3-stage cp.async (1 sync/slab), smem [mn][k] stride 20.
// nrm: 0 raw, 1 round, 2 norm+round, 3 norm+w+rope+round, 4 = 3 + QSCALE.
// rows >= rowlim stored raw. N-tile (128) == one head for norm modes.
struct GemmB {
    const float* A[8]; const float* Bm[8]; const float* bias[8]; float* C[8];
    const float* w[8];
    int M[8], N[8], K[8], nrm[8], rowlim[8], tokoff[8];
};

template <bool ACC>
__global__ __launch_bounds__(256, 2) void gemm_tc(GemmB P, const float* cs, const float* sn)
{
    extern __shared__ unsigned smg[];
    unsigned* As = smg;              // 3 stages x 2560
    unsigned* Bs = smg + 3 * 2560;   // 3 stages x 2560

    const int z = blockIdx.z;
    const int M = P.M[z], N = P.N[z], K = P.K[z];
    const int bm = blockIdx.y << 7, bn = blockIdx.x << 7;
    if (bm >= M || bn >= N) return;
    const float* A = P.A[z];
    const float* Bw = P.Bm[z];
    const float* bias = P.bias[z];
    float* C = P.C[z];
    const float* wp = P.w[z];
    const int mode = (bm >= P.rowlim[z]) ? 0 : P.nrm[z];
    const int tokoff = P.tokoff[z];

    const int tid = threadIdx.x;
    const int lw = tid & 31, w = tid >> 5, g = lw >> 2, t = lw & 3;
    const int wm = w & 1, wn = w >> 1;   // 2 x 4 warp grid, warp tile 64x32

    const int lrow = tid >> 1, lseg = (tid & 1) * 8;
    const float* Arow = A + (size_t)(bm + lrow) * K + lseg;
    const float* Brow = Bw + (size_t)(bn + lrow) * K + lseg;
    const unsigned as_u = (unsigned)__cvta_generic_to_shared(As) + (lrow * 20 + lseg) * 4;
    const unsigned bs_u = (unsigned)__cvta_generic_to_shared(Bs) + (lrow * 20 + lseg) * 4;

    float acc[4][4][4];
#pragma unroll
    for (int mt = 0; mt < 4; mt++)
#pragma unroll
        for (int nt = 0; nt < 4; nt++)
#pragma unroll
            for (int i = 0; i < 4; i++) acc[mt][nt][i] = 0.f;

    const int niter = K >> 4;
    // prefetch stages 0,1
    cpa16(as_u, Arow);              cpa16(as_u + 16, Arow + 4);
    cpa16(bs_u, Brow);              cpa16(bs_u + 16, Brow + 4);
    cp_commit();
    {
        const unsigned off = 2560u * 4u;
        cpa16(as_u + off, Arow + 16);   cpa16(as_u + off + 16, Arow + 20);
        cpa16(bs_u + off, Brow + 16);   cpa16(bs_u + off + 16, Brow + 20);
        cp_commit();
    }

    int st = 0, ld = 2;
    for (int it = 0; it < niter; it++) {
        if (it + 1 < niter) cp_wait1(); else cp_wait0();
        __syncthreads();
        if (it + 2 < niter) {
            const int k0 = (it + 2) << 4;
            const unsigned off = (unsigned)(ld * 2560 * 4);
            cpa16(as_u + off, Arow + k0);   cpa16(as_u + off + 16, Arow + k0 + 4);
            cpa16(bs_u + off, Brow + k0);   cpa16(bs_u + off + 16, Brow + k0 + 4);
            cp_commit();
            ld = (ld == 2) ? 0 : ld + 1;
        }
        const unsigned* Ac = As + st * 2560;
        const unsigned* Bc = Bs + st * 2560;
        st = (st == 2) ? 0 : st + 1;
#pragma unroll
        for (int ks = 0; ks < 2; ks++) {
            const int kr = ks * 8 + t;
            unsigned af[4][4], bf[4][2];
#pragma unroll
            for (int mt = 0; mt < 4; mt++) {
                const unsigned* ap = Ac + (wm * 64 + mt * 16 + g) * 20 + kr;
                af[mt][0] = ap[0];
                af[mt][1] = ap[160];
                af[mt][2] = ap[4];
                af[mt][3] = ap[164];
            }
#pragma unroll
            for (int nt = 0; nt < 4; nt++) {
                const unsigned* bp = Bc + (wn * 32 + nt * 8 + g) * 20 + kr;
                bf[nt][0] = bp[0];
                bf[nt][1] = bp[4];
            }
#pragma unroll
            for (int mt = 0; mt < 4; mt++)
#pragma unroll
                for (int nt = 0; nt < 4; nt++)
                    mma8(acc[mt][nt], af[mt], bf[nt][0], bf[nt][1]);
        }
    }

    // ---- epilogue: bias/ACC, then optional norm/rope/round ----
#pragma unroll
    for (int mt = 0; mt < 4; mt++) {
        const int r0 = bm + wm * 64 + mt * 16 + g;
        const int r1 = r0 + 8;
#pragma unroll
        for (int nt = 0; nt < 4; nt++) {
            const int cc = bn + wn * 32 + nt * 8 + 2 * t;
            if (bias) {
                float bx = bias[cc], by = bias[cc + 1];
                acc[mt][nt][0] += bx; acc[mt][nt][1] += by;
                acc[mt][nt][2] += bx; acc[mt][nt][3] += by;
            }
            if (ACC) {
                float2 e0 = *(const float2*)(C + (size_t)r0 * N + cc);
                float2 e1 = *(const float2*)(C + (size_t)r1 * N + cc);
                acc[mt][nt][0] += e0.x; acc[mt][nt][1] += e0.y;
                acc[mt][nt][2] += e1.x; acc[mt][nt][3] += e1.y;
            }
        }
    }

    float inv0[4], inv1[4];
    if (mode >= 2) {
        __syncthreads();   // smem stages no longer needed; reuse as reduce buffer
        float* ssb = (float*)smg;   // [128 rows][4 wn]
#pragma unroll
        for (int mt = 0; mt < 4; mt++) {
            float s0 = 0.f, s1 = 0.f;
#pragma unroll
            for (int nt = 0; nt < 4; nt++) {
                s0 += acc[mt][nt][0] * acc[mt][nt][0] + acc[mt][nt][1] * acc[mt][nt][1];
                s1 += acc[mt][nt][2] * acc[mt][nt][2] + acc[mt][nt][3] * acc[mt][nt][3];
            }
            s0 += __shfl_xor_sync(0xffffffffu, s0, 1);
            s0 += __shfl_xor_sync(0xffffffffu, s0, 2);
            s1 += __shfl_xor_sync(0xffffffffu, s1, 1);
            s1 += __shfl_xor_sync(0xffffffffu, s1, 2);
            if (t == 0) {
                const int rr = wm * 64 + mt * 16 + g;
                ssb[rr * 4 + wn] = s0;
                ssb[(rr + 8) * 4 + wn] = s1;
            }
        }
        __syncthreads();
#pragma unroll
        for (int mt = 0; mt < 4; mt++) {
            const int rr = wm * 64 + mt * 16 + g;
            float4 a = ((const float4*)ssb)[rr];
            float4 b = ((const float4*)ssb)[rr + 8];
            inv0[mt] = rsqrtf((a.x + a.y + a.z + a.w) * (1.0f / HDIM) + EPSV);
            inv1[mt] = rsqrtf((b.x + b.y + b.z + b.w) * (1.0f / HDIM) + EPSV);
        }
    }

#pragma unroll
    for (int mt = 0; mt < 4; mt++) {
        const int r0 = bm + wm * 64 + mt * 16 + g;
        const int r1 = r0 + 8;
#pragma unroll
        for (int nt = 0; nt < 4; nt++) {
            const int d = wn * 32 + nt * 8 + 2 * t;   // col within head (N-tile==head)
            const int cc = bn + d;
            float2 v0 = make_float2(acc[mt][nt][0], acc[mt][nt][1]);
            float2 v1 = make_float2(acc[mt][nt][2], acc[mt][nt][3]);
            if (mode >= 2) {
                v0.x *= inv0[mt]; v0.y *= inv0[mt];
                v1.x *= inv1[mt]; v1.y *= inv1[mt];
                if (wp) {
                    float2 ww = *(const float2*)(wp + d);
                    v0.x *= ww.x; v0.y *= ww.y;
                    v1.x *= ww.x; v1.y *= ww.y;
                }
            }
            if (mode >= 3) {
                const size_t t0 = (size_t)(tokoff + r0) * HDIM + d;
                const size_t t1 = (size_t)(tokoff + r1) * HDIM + d;
                float2 c0 = *(const float2*)(cs + t0);
                float2 s0v = *(const float2*)(sn + t0);
                float2 c1 = *(const float2*)(cs + t1);
                float2 s1v = *(const float2*)(sn + t1);
                float e0 = v0.x * c0.x - v0.y * s0v.x;
                float o0 = v0.y * c0.y + v0.x * s0v.y;
                float e1 = v1.x * c1.x - v1.y * s1v.x;
                float o1 = v1.y * c1.y + v1.x * s1v.y;
                v0.x = e0; v0.y = o0; v1.x = e1; v1.y = o1;
            }
            if (mode == 4) {
                v0.x *= QSCALE; v0.y *= QSCALE;
                v1.x *= QSCALE; v1.y *= QSCALE;
            }
            if (mode >= 1) {
                v0.x = __uint_as_float(f2tf(v0.x));
                v0.y = __uint_as_float(f2tf(v0.y));
                v1.x = __uint_as_float(f2tf(v1.x));
                v1.y = __uint_as_float(f2tf(v1.y));
            }
            *(float2*)(C + (size_t)r0 * N + cc) = v0;
            *(float2*)(C + (size_t)r1 * N + cc) = v1;
        }
    }
}

// ============ fused flash attention (tf32, pre-rounded operands) ============
// Bq=128 (8 warps x 16 q), Bk=64, HD=128. Phase 0: main (block-masked) writes Out;
// Phase 1: IP (kv=128) RMW-adds into Out. Q fragments live across both phases.
__global__ __launch_bounds__(256, 1) void attn_tc(
    const unsigned* __restrict__ Q, const unsigned* __restrict__ Km,
    const unsigned* __restrict__ Vm, const unsigned* __restrict__ Ki,
    const unsigned* __restrict__ Vi, float* __restrict__ Out)
{
    extern __shared__ unsigned smu[];
    unsigned* Ks = smu;
    unsigned* Vs = smu + 2 * 8448;
    unsigned* Ps = Vs + 2 * 8704;

    const int tid = threadIdx.x;
    const int l = tid & 31, w = tid >> 5;
    const int g = l >> 2, t = l & 3;
    const int h = blockIdx.y;
    const int q0 = blockIdx.x << 7;
    const int qr = q0 + w * 16 + g;

    unsigned qf[16][4];
    {
        const unsigned* qp = Q + (size_t)qr * D_MODEL + h * HDIM;
        const unsigned* qp8 = qp + (size_t)8 * D_MODEL;
#pragma unroll
        for (int ks = 0; ks < 16; ks++) {
            const int cb = ks * 8 + t;
            qf[ks][0] = qp[cb];
            qf[ks][1] = qp8[cb];
            qf[ks][2] = qp[cb + 4];
            qf[ks][3] = qp8[cb + 4];
        }
    }

    const int row = tid >> 2, seg = (tid & 3) * 32;
    const unsigned ks_u = (unsigned)__cvta_generic_to_shared(Ks) + (row * 132 + seg) * 4;
    const unsigned vs_u = (unsigned)__cvta_generic_to_shared(Vs) + (row * 136 + seg) * 4;
    float* op0 = Out + (size_t)qr * D_MODEL + h * HDIM;
    float* op1 = op0 + (size_t)8 * D_MODEL;

#pragma unroll 1
    for (int ph = 0; ph < 2; ph++) {
        const unsigned* Kb = ph ? Ki : Km;
        const unsigned* Vb = ph ? Vi : Vm;
        const int kt0 = (ph == 0 && q0 >= BLOCK_TOK) ? BLOCK_TOK : 0;
        const int ntiles = ((ph ? T_IPN : S_TOK) - kt0) >> 6;

        float o[16][4];
#pragma unroll
        for (int nt = 0; nt < 16; nt++)
#pragma unroll
            for (int i = 0; i < 4; i++) o[nt][i] = 0.f;
        float mrow0 = -1e30f, mrow1 = -1e30f, lrow0 = 0.f, lrow1 = 0.f;

        __syncthreads();
        {
            const unsigned* kg = Kb + (size_t)(kt0 + row) * D_MODEL + h * HDIM + seg;
            const unsigned* vg = Vb + (size_t)(kt0 + row) * D_MODEL + h * HDIM + seg;
#pragma unroll
            for (int c = 0; c < 8; c++) {
                cpa16(ks_u + c * 16, kg + c * 4);
                cpa16(vs_u + c * 16, vg + c * 4);
            }
            cp_commit();
        }

        for (int it = 0; it < ntiles; it++) {
            const int cur = it & 1;
            cp_wait0();
            __syncthreads();
            if (it + 1 < ntiles) {
                const int kt = kt0 + (it + 1) * 64;
                const unsigned* kg = Kb + (size_t)(kt + row) * D_MODEL + h * HDIM + seg;
                const unsigned* vg = Vb + (size_t)(kt + row) * D_MODEL + h * HDIM + seg;
                const unsigned ko = ks_u + (cur ^ 1) * 8448 * 4;
                const unsigned vo = vs_u + (cur ^ 1) * 8704 * 4;
#pragma unroll
                for (int c = 0; c < 8; c++) {
                    cpa16(ko + c * 16, kg + c * 4);
                    cpa16(vo + c * 16, vg + c * 4);
                }
                cp_commit();
            }
            const unsigned* Kc = Ks + cur * 8448;
            const unsigned* Vc = Vs + cur * 8704;

            float s[8][4];
#pragma unroll
            for (int nt = 0; nt < 8; nt++)
#pragma unroll
                for (int i = 0; i < 4; i++) s[nt][i] = 0.f;
#pragma unroll
            for (int ks = 0; ks < 16; ks++) {
                const int kr = ks * 8 + t;
#pragma unroll
                for (int nt = 0; nt < 8; nt++) {
                    const unsigned* kp2 = Kc + (nt * 8 + g) * 132 + kr;
                    mma8(s[nt], qf[ks], kp2[0], kp2[4]);
                }
            }

            float mx0 = -1e30f, mx1 = -1e30f;
#pragma unroll
            for (int nt = 0; nt < 8; nt++) {
                mx0 = fmaxf(mx0, fmaxf(s[nt][0], s[nt][1]));
                mx1 = fmaxf(mx1, fmaxf(s[nt][2], s[nt][3]));
            }
            mx0 = fmaxf(mx0, __shfl_xor_sync(0xffffffffu, mx0, 1));
            mx0 = fmaxf(mx0, __shfl_xor_sync(0xffffffffu, mx0, 2));
            mx1 = fmaxf(mx1, __shfl_xor_sync(0xffffffffu, mx1, 1));
            mx1 = fmaxf(mx1, __shfl_xor_sync(0xffffffffu, mx1, 2));
            const float mn0 = fmaxf(mrow0, mx0), mn1 = fmaxf(mrow1, mx1);
            const float al0 = exp2f(mrow0 - mn0), al1 = exp2f(mrow1 - mn1);
            mrow0 = mn0; mrow1 = mn1;

            float sum0 = 0.f, sum1 = 0.f;
#pragma unroll
            for (int nt = 0; nt < 8; nt++) {
                float p0 = exp2f(s[nt][0] - mn0);
                float p1 = exp2f(s[nt][1] - mn0);
                float p2 = exp2f(s[nt][2] - mn1);
                float p3 = exp2f(s[nt][3] - mn1);
                sum0 += p0 + p1;
                sum1 += p2 + p3;
                const int nb = nt * 8 + 2 * t;
                Ps[(nb + 0) * 136 + w * 16 + g]     = f2tf(p0);
                Ps[(nb + 1) * 136 + w * 16 + g]     = f2tf(p1);
                Ps[(nb + 0) * 136 + w * 16 + g + 8] = f2tf(p2);
                Ps[(nb + 1) * 136 + w * 16 + g + 8] = f2tf(p3);
            }
            sum0 += __shfl_xor_sync(0xffffffffu, sum0, 1);
            sum0 += __shfl_xor_sync(0xffffffffu, sum0, 2);
            sum1 += __shfl_xor_sync(0xffffffffu, sum1, 1);
            sum1 += __shfl_xor_sync(0xffffffffu, sum1, 2);
            lrow0 = lrow0 * al0 + sum0;
            lrow1 = lrow1 * al1 + sum1;
#pragma unroll
            for (int nt = 0; nt < 16; nt++) {
                o[nt][0] *= al0; o[nt][1] *= al0;
                o[nt][2] *= al1; o[nt][3] *= al1;
            }
            __syncwarp();

#pragma unroll
            for (int ks = 0; ks < 8; ks++) {
                const int kr = ks * 8 + t;
                unsigned pa[4];
                pa[0] = Ps[kr * 136 + w * 16 + g];
                pa[1] = Ps[kr * 136 + w * 16 + g + 8];
                pa[2] = Ps[(kr + 4) * 136 + w * 16 + g];
                pa[3] = Ps[(kr + 4) * 136 + w * 16 + g + 8];
#pragma unroll
                for (int nt = 0; nt < 16; nt++) {
                    const unsigned* vp2 = Vc + kr * 136 + nt * 8 + g;
                    mma8(o[nt], pa, vp2[0], vp2[4 * 136]);
                }
            }
        }

        const float inv0 = 1.f / lrow0, inv1 = 1.f / lrow1;
#pragma unroll
        for (int nt = 0; nt < 16; nt++) {
            const int cc = nt * 8 + 2 * t;
            float2 v0 = make_float2(o[nt][0] * inv0, o[nt][1] * inv0);
            float2 v1 = make_float2(o[nt][2] * inv1, o[nt][3] * inv1);
            if (ph == 1) {
                float2 e0 = *(const float2*)(op0 + cc);
                float2 e1 = *(const float2*)(op1 + cc);
                v0.x += e0.x; v0.y += e0.y; v1.x += e1.x; v1.y += e1.y;
            }
            *(float2*)(op0 + cc) = v0;
            *(float2*)(op1 + cc) = v1;
        }
    }
}

// ---------------- host launcher ----------------
extern "C" void kernel_launch(void* const* d_in, const int* in_sizes, int n_in,
                              void* d_out, int out_size)
{
    (void)in_sizes; (void)n_in; (void)out_size;
    const float* x    = (const float*)d_in[0];
    const float* img  = (const float*)d_in[1];
    const float* cosr = (const float*)d_in[2];
    const float* sinr = (const float*)d_in[3];
    const float* Wq   = (const float*)d_in[4];
    const float* bq   = (const float*)d_in[5];
    const float* Wk   = (const float*)d_in[6];
    const float* bk   = (const float*)d_in[7];
    const float* Wv   = (const float*)d_in[8];
    const float* bv   = (const float*)d_in[9];
    const float* qd   = (const float*)d_in[10];
    const float* qu   = (const float*)d_in[11];
    const float* kd   = (const float*)d_in[12];
    const float* ku   = (const float*)d_in[13];
    const float* vd   = (const float*)d_in[14];
    const float* vu   = (const float*)d_in[15];
    const float* nqw  = (const float*)d_in[16];
    const float* nkw  = (const float*)d_in[17];
    const float* Wkip = (const float*)d_in[18];
    const float* Wvip = (const float*)d_in[19];
    float* out = (float*)d_out;

    float *q, *k, *v, *kip, *vip, *lt;
    float *xr, *wqr, *wkr, *wvr, *imgr, *wkipr, *wvipr, *ldr;
    cudaGetSymbolAddress((void**)&q,     g_q);
    cudaGetSymbolAddress((void**)&k,     g_k);
    cudaGetSymbolAddress((void**)&v,     g_v);
    cudaGetSymbolAddress((void**)&kip,   g_kip);
    cudaGetSymbolAddress((void**)&vip,   g_vip);
    cudaGetSymbolAddress((void**)&lt,    g_lt);
    cudaGetSymbolAddress((void**)&xr,    g_xr);
    cudaGetSymbolAddress((void**)&wqr,   g_wqr);
    cudaGetSymbolAddress((void**)&wkr,   g_wkr);
    cudaGetSymbolAddress((void**)&wvr,   g_wvr);
    cudaGetSymbolAddress((void**)&imgr,  g_imgr);
    cudaGetSymbolAddress((void**)&wkipr, g_wkipr);
    cudaGetSymbolAddress((void**)&wvipr, g_wvipr);
    cudaGetSymbolAddress((void**)&ldr,   g_ldr);

    const int LW = RANKN * D_MODEL;
    float* qdr = ldr;            float* kdr = ldr + LW;     float* vdr = ldr + 2 * LW;
    float* qur = ldr + 3 * LW;   float* kur = ldr + 4 * LW; float* vur = ldr + 5 * LW;

    const int GSM = 6 * 2560 * 4;   // 61.4 KB dynamic smem (3 stages A+B)
    cudaFuncSetAttribute(gemm_tc<false>, cudaFuncAttributeMaxDynamicSharedMemorySize, GSM);
    cudaFuncSetAttribute(gemm_tc<true>,  cudaFuncAttributeMaxDynamicSharedMemorySize, GSM);

    // 1) RNA tf32 rounding pre-pass (13 buffers)
    {
        R16 R;
        R.s[0]  = x;    R.d[0]  = xr;    R.n[0]  = S_TOK * D_MODEL;
        R.s[1]  = Wq;   R.d[1]  = wqr;   R.n[1]  = D_MODEL * D_MODEL;
        R.s[2]  = Wk;   R.d[2]  = wkr;   R.n[2]  = D_MODEL * D_MODEL;
        R.s[3]  = Wv;   R.d[3]  = wvr;   R.n[3]  = D_MODEL * D_MODEL;
        R.s[4]  = img;  R.d[4]  = imgr;  R.n[4]  = T_IPN * D_IPN;
        R.s[5]  = Wkip; R.d[5]  = wkipr; R.n[5]  = D_MODEL * D_IPN;
        R.s[6]  = Wvip; R.d[6]  = wvipr; R.n[6]  = D_MODEL * D_IPN;
        R.s[7]  = qd;   R.d[7]  = qdr;   R.n[7]  = LW;
        R.s[8]  = kd;   R.d[8]  = kdr;   R.n[8]  = LW;
        R.s[9]  = vd;   R.d[9]  = vdr;   R.n[9]  = LW;
        R.s[10] = qu;   R.d[10] = qur;   R.n[10] = LW;
        R.s[11] = ku;   R.d[11] = kur;   R.n[11] = LW;
        R.s[12] = vu;   R.d[12] = vur;   R.n[12] = LW;
        round_tf32_kernel<<<dim3(512, 13), 256>>>(R);
    }
    const float* xcr = xr + (size_t)BLOCK_TOK * D_MODEL;

    // 2) mega GEMM: z0-2 QKV (norm fused, rows<2048), z3-5 LoRA-down, z6-7 IP proj
    {
        GemmB P;
        P.A[0] = xr; P.A[1] = xr; P.A[2] = xr;
        P.Bm[0] = wqr; P.Bm[1] = wkr; P.Bm[2] = wvr;
        P.bias[0] = bq; P.bias[1] = bk; P.bias[2] = bv;
        P.C[0] = q;  P.C[1] = k;  P.C[2] = v;
        P.w[0] = nqw; P.w[1] = nkw; P.w[2] = nullptr;
        P.M[0] = P.M[1] = P.M[2] = S_TOK;
        P.N[0] = P.N[1] = P.N[2] = D_MODEL;
        P.K[0] = P.K[1] = P.K[2] = D_MODEL;
        P.nrm[0] = 4; P.nrm[1] = 3; P.nrm[2] = 1;
        P.rowlim[0] = P.rowlim[1] = P.rowlim[2] = BLOCK_TOK;
        P.tokoff[0] = P.tokoff[1] = P.tokoff[2] = 0;
        P.A[3] = xcr; P.A[4] = xcr; P.A[5] = xcr;
        P.Bm[3] = qdr; P.Bm[4] = kdr; P.Bm[5] = vdr;
        P.bias[3] = P.bias[4] = P.bias[5] = nullptr;
        P.C[3] = lt; P.C[4] = lt + CONDN * RANKN; P.C[5] = lt + 2 * CONDN * RANKN;
        P.w[3] = P.w[4] = P.w[5] = nullptr;
        P.M[3] = P.M[4] = P.M[5] = CONDN;
        P.N[3] = P.N[4] = P.N[5] = RANKN;
        P.K[3] = P.K[4] = P.K[5] = D_MODEL;
        P.nrm[3] = P.nrm[4] = P.nrm[5] = 1;
        P.rowlim[3] = P.rowlim[4] = P.rowlim[5] = BIGROW;
        P.tokoff[3] = P.tokoff[4] = P.tokoff[5] = 0;
        P.A[6] = imgr; P.A[7] = imgr;
        P.Bm[6] = wkipr; P.Bm[7] = wvipr;
        P.bias[6] = P.bias[7] = nullptr;
        P.C[6] = kip; P.C[7] = vip;
        P.w[6] = P.w[7] = nullptr;
        P.M[6] = P.M[7] = T_IPN;
        P.N[6] = P.N[7] = D_MODEL;
        P.K[6] = P.K[7] = D_IPN;
        P.nrm[6] = 2; P.nrm[7] = 1;
        P.rowlim[6] = P.rowlim[7] = BIGROW;
        P.tokoff[6] = P.tokoff[7] = 0;
        gemm_tc<false><<<dim3(D_MODEL / 128, S_TOK / 128, 8), 256, GSM>>>(P, cosr, sinr);
    }
    // 3) LoRA up: accumulate into q/k/v cond rows, then fused norm+rope+round
    {
        GemmB P;
        P.A[0] = lt; P.A[1] = lt + CONDN * RANKN; P.A[2] = lt + 2 * CONDN * RANKN;
        P.Bm[0] = qur; P.Bm[1] = kur; P.Bm[2] = vur;
        P.bias[0] = P.bias[1] = P.bias[2] = nullptr;
        P.C[0] = q + (size_t)BLOCK_TOK * D_MODEL;
        P.C[1] = k + (size_t)BLOCK_TOK * D_MODEL;
        P.C[2] = v + (size_t)BLOCK_TOK * D_MODEL;
        P.w[0] = nqw; P.w[1] = nkw; P.w[2] = nullptr;
        for (int i = 0; i < 3; i++) {
            P.M[i] = CONDN; P.N[i] = D_MODEL; P.K[i] = RANKN;
            P.rowlim[i] = BIGROW; P.tokoff[i] = BLOCK_TOK;
        }
        P.nrm[0] = 4; P.nrm[1] = 3; P.nrm[2] = 1;
        for (int i = 3; i < 8; i++) {
            P.A[i] = nullptr; P.Bm[i] = nullptr; P.bias[i] = nullptr; P.C[i] = nullptr;
            P.w[i] = nullptr; P.M[i] = 0; P.N[i] = 0; P.K[i] = 16;
            P.nrm[i] = 0; P.rowlim[i] = BIGROW; P.tokoff[i] = 0;
        }
        gemm_tc<true><<<dim3(D_MODEL / 128, CONDN / 128, 3), 256, GSM>>>(P, cosr, sinr);
    }
    // 4) fused attention: main (masked) + IP phase
    {
        size_t smem = (size_t)(2 * 8448 + 2 * 8704 + 64 * 136) * 4;
        cudaFuncSetAttribute(attn_tc, cudaFuncAttributeMaxDynamicSharedMemorySize, (int)smem);
        attn_tc<<<dim3(S_TOK / 128, NHEAD), 256, smem>>>(
            (const unsigned*)q, (const unsigned*)k, (const unsigned*)v,
            (const unsigned*)kip, (const unsigned*)vip, out);
    }
}